// round 12
// baseline (speedup 1.0000x reference)
#include <cuda_runtime.h>
#include <cstdint>

// Fixed shapes: B=2, C=16, NVOX = 64*128*128 = 2^20
#define NVOX   (1 << 20)
#define NCLS   16
#define NB     2
#define THREADS 256
#define BLK_PER_B 148
#define NBLK   (NB * BLK_PER_B)            // 296 = exactly 2 blocks/SM, 1 wave
#define TSTG   256                         // voxels per pipeline stage
#define STG_PER_B (NVOX / TSTG)            // 4096 stages per batch
#define XB_BYTES (NCLS * TSTG * 4)         // 16384 B of logits per stage
#define STAGE_BYTES (XB_BYTES + TSTG * 8)  // + up to 2KB labels = 18432
#define NBUF   4
#define DYN_BYTES (NBUF * STAGE_BYTES)     // 73728
#define PF     5                           // prefetch leads smem-copy by 5 stages

// Device-global scratch (zero-init at load; last block re-zeros post-finalize).
__device__ float    g_sum[NB * NCLS];
__device__ float    g_cnt[NB * NCLS];
__device__ unsigned g_ticket;

extern __shared__ char dynsmem[];

__device__ __forceinline__ void cp16(uint32_t dst, const void* src) {
    asm volatile("cp.async.cg.shared.global [%0], [%1], 16;" :: "r"(dst), "l"(src));
}
__device__ __forceinline__ void pf_l2(const void* src, uint32_t bytes) {
    asm volatile("cp.async.bulk.prefetch.L2.global [%0], %1;"
                 :: "l"(src), "r"(bytes) : "memory");
}

__global__ __launch_bounds__(THREADS, 2)
void ce_pf_kernel(const float* __restrict__ x, const char* __restrict__ y,
                  float* __restrict__ out) {
    __shared__ float s_bin[NCLS][THREADS];   // bank = tid%32 -> conflict-free
    __shared__ int   sh_y64, sh_last;

    const int tid = threadIdx.x;
    const int blk = blockIdx.x;
    const int b   = (blk >= BLK_PER_B) ? 1 : 0;
    const int bb  = blk - b * BLK_PER_B;
    const uint32_t smem_u32 = (uint32_t)__cvta_generic_to_shared(dynsmem);

    // Label dtype detect first (int64 LE => odd int32 words all 0, labels<16).
    if (tid < 32) {
        int v = ((const int*)y)[2 * tid + 1];
        unsigned nz = __ballot_sync(0xffffffffu, v != 0);
        if (tid == 0) sh_y64 = (nz == 0u) ? 1 : 0;
    }
    __syncthreads();
    const bool y64 = (sh_y64 != 0);

    // Interleaved stage ownership (proven best): sl = bb + i*148 (27|28 stages).
    const int nIter = (STG_PER_B - bb + BLK_PER_B - 1) / BLK_PER_B;
    const float* xb = x + (size_t)b * NCLS * NVOX;
    const char*  yb = y + ((size_t)b * NVOX << (y64 ? 3 : 2));
    const int      yshift = y64 ? 3 : 2;
    const uint32_t lbytes = y64 ? (TSTG * 8) : (TSTG * 4);

    auto issue = [&](int i) {
        const int off = (bb + i * BLK_PER_B) * TSTG;
        const uint32_t sb = smem_u32 + (uint32_t)((i & (NBUF - 1)) * STAGE_BYTES);
        const int lane64 = tid & 63, grp = tid >> 6;
#pragma unroll
        for (int r = 0; r < 4; r++) {
            const int c = 4 * r + grp;   // 64 threads copy one 1KB class row
            cp16(sb + (uint32_t)(c * (TSTG * 4) + lane64 * 16),
                 xb + (size_t)c * NVOX + off + lane64 * 4);
        }
        if (y64) {
            if (tid < 128)
                cp16(sb + XB_BYTES + tid * 16, yb + (size_t)off * 8 + tid * 16);
        } else {
            if (tid < 64)
                cp16(sb + XB_BYTES + tid * 16, yb + (size_t)off * 4 + tid * 16);
        }
    };
    // Threads 0..16 prefetch stage s into L2 (1KB per class + labels).
    auto prefetch = [&](int s) {
        const int off = (bb + s * BLK_PER_B) * TSTG;
        if (tid < NCLS)       pf_l2(xb + (size_t)tid * NVOX + off, TSTG * 4);
        else if (tid == NCLS) pf_l2(yb + ((size_t)off << yshift), lbytes);
    };

    // Prologue: 3 smem stages in flight + L2 prefetch for stages 3..7.
#pragma unroll
    for (int k = 0; k < NBUF - 1; k++) {            // nIter >= 27 always
        issue(k);
        asm volatile("cp.async.commit_group;" ::: "memory");
    }
    if (tid <= NCLS) {
#pragma unroll
        for (int k = NBUF - 1; k < NBUF - 1 + PF; k++) prefetch(k);
    }

    // Zero bins while the first copies/prefetches fly.
#pragma unroll
    for (int c = 0; c < NCLS; c++) s_bin[c][tid] = 0.0f;

    // Counts: classes 0-7 in cLo byte lanes, 8-15 in cHi (max 28 <= 255).
    unsigned long long cLo = 0ull, cHi = 0ull;

    for (int i = 0; i < nIter; i++) {
        asm volatile("cp.async.wait_group 2;" ::: "memory");  // stage i landed
        __syncthreads();
        // Refill buffer (i+3)&3 == (i-1)&3, consumed in iter i-1.
        if (i + NBUF - 1 < nIter) issue(i + NBUF - 1);
        asm volatile("cp.async.commit_group;" ::: "memory");
        // L2 prefetch leading the smem copy by PF stages.
        if (i + NBUF - 1 + PF < nIter) prefetch(i + NBUF - 1 + PF);

        const char*  stg = dynsmem + (size_t)(i & (NBUF - 1)) * STAGE_BYTES;
        const float* xt  = (const float*)stg;
        const int lab = y64 ? ((const int*)(stg + XB_BYTES))[2 * tid]
                            : ((const int*)(stg + XB_BYTES))[tid];

        float a0 = 0.f, a1 = 0.f, a2 = 0.f, a3 = 0.f;
#pragma unroll
        for (int c = 0; c < NCLS; c += 4) {
            a0 += __expf(xt[(c + 0) * TSTG + tid]);
            a1 += __expf(xt[(c + 1) * TSTG + tid]);
            a2 += __expf(xt[(c + 2) * TSTG + tid]);
            a3 += __expf(xt[(c + 3) * TSTG + tid]);
        }
        const float xl  = xt[lab * TSTG + tid];          // bank tid%32: clean
        const float nll = __logf((a0 + a1) + (a2 + a3)) - xl;

        s_bin[lab][tid] += nll;
        if (lab < 8) cLo += 1ull << (lab * 8);
        else         cHi += 1ull << ((lab - 8) * 8);
    }
    __syncthreads();

    // Phase 1: reduce nll bins. Warp w handles labs {w, w+8}.
    const int w = tid >> 5, l = tid & 31;
#pragma unroll
    for (int lab = w; lab < NCLS; lab += 8) {
        float fs = 0.0f;
#pragma unroll
        for (int k = 0; k < 8; k++) fs += s_bin[lab][l + 32 * k];
#pragma unroll
        for (int o = 16; o > 0; o >>= 1)
            fs += __shfl_xor_sync(0xffffffffu, fs, o);
        if (l == 0) atomicAdd(&g_sum[b * NCLS + lab], fs);
    }
    __syncthreads();

    // Phase 2: reuse s_bin for counts (thread-private slots: plain stores).
#pragma unroll
    for (int c = 0; c < NCLS; c++) {
        const unsigned cc = (unsigned)(((c < 8 ? cLo : cHi) >> ((c & 7) * 8)) & 0xffull);
        s_bin[c][tid] = (float)cc;
    }
    __syncthreads();
#pragma unroll
    for (int lab = w; lab < NCLS; lab += 8) {
        float fs = 0.0f;
#pragma unroll
        for (int k = 0; k < 8; k++) fs += s_bin[lab][l + 32 * k];
#pragma unroll
        for (int o = 16; o > 0; o >>= 1)
            fs += __shfl_xor_sync(0xffffffffu, fs, o);
        if (l == 0) atomicAdd(&g_cnt[b * NCLS + lab], fs);
    }

    // Last-block finalize.
    __threadfence();
    if (tid == 0) {
        unsigned t = atomicAdd(&g_ticket, 1u);
        sh_last = (t == (unsigned)(NBLK - 1)) ? 1 : 0;
    }
    __syncthreads();

    if (sh_last) {
        __threadfence();
        if (tid < NB * NCLS) {
            const float s = atomicAdd(&g_sum[tid], 0.0f);
            const float c = atomicAdd(&g_cnt[tid], 0.0f);
            float m = (c > 0.0f) ? (s / c) : 0.0f;
#pragma unroll
            for (int o = 16; o > 0; o >>= 1)
                m += __shfl_xor_sync(0xffffffffu, m, o);
            if (tid == 0) {
                out[0] = m / (float)(NB * NCLS);
                g_ticket = 0u;
            }
            g_sum[tid] = 0.0f;
            g_cnt[tid] = 0.0f;
        }
    }
}

extern "C" void kernel_launch(void* const* d_in, const int* in_sizes, int n_in,
                              void* d_out, int out_size) {
    const float* x = (const float*)d_in[0];
    const char*  y = (const char*)d_in[1];
    cudaFuncSetAttribute(ce_pf_kernel,
                         cudaFuncAttributeMaxDynamicSharedMemorySize, DYN_BYTES);
    ce_pf_kernel<<<NBLK, THREADS, DYN_BYTES>>>(x, y, (float*)d_out);
}

// round 13
// speedup vs baseline: 1.2062x; 1.2062x over previous
#include <cuda_runtime.h>
#include <cstdint>

// Fixed shapes: B=2, C=16, NVOX = 64*128*128 = 2^20
#define NVOX   (1 << 20)
#define NCLS   16
#define NB     2
#define THREADS 256
#define BLK_PER_B 148
#define NBLK   (NB * BLK_PER_B)            // 296 = exactly 2 blocks/SM, 1 wave
#define TSTG   256                         // voxels per pipeline stage
#define STG_PER_B (NVOX / TSTG)            // 4096 stages per batch
#define XB_BYTES (NCLS * TSTG * 4)         // 16384 B of logits per stage
#define STAGE_BYTES (XB_BYTES + TSTG * 8)  // + up to 2KB labels = 18432
#define NBUF   4
#define DYN_BYTES (NBUF * STAGE_BYTES)     // 73728

// Device-global scratch (zero-init at load; last block re-zeros post-finalize).
__device__ float    g_sum[NB * NCLS];
__device__ float    g_cnt[NB * NCLS];
__device__ unsigned g_ticket;

extern __shared__ char dynsmem[];

__device__ __forceinline__ void cp16(uint32_t dst, const void* src) {
    asm volatile("cp.async.cg.shared.global [%0], [%1], 16;" :: "r"(dst), "l"(src));
}

__global__ __launch_bounds__(THREADS, 2)
void ce_pipe_kernel(const float* __restrict__ x, const char* __restrict__ y,
                    float* __restrict__ out) {
    __shared__ float s_bin[NCLS][THREADS];   // bank = tid%32 -> conflict-free
    __shared__ int   sh_y64, sh_last;

    const int tid = threadIdx.x;
    const int blk = blockIdx.x;
    const int b   = (blk >= BLK_PER_B) ? 1 : 0;
    const int bb  = blk - b * BLK_PER_B;
    const uint32_t smem_u32 = (uint32_t)__cvta_generic_to_shared(dynsmem);

    // Label dtype detect FIRST (int64 LE => odd int32 words all 0, labels<16).
    if (tid < 32) {
        int v = ((const int*)y)[2 * tid + 1];
        unsigned nz = __ballot_sync(0xffffffffu, v != 0);
        if (tid == 0) sh_y64 = (nz == 0u) ? 1 : 0;
    }
    __syncthreads();
    const bool y64 = (sh_y64 != 0);

    // Interleaved stage ownership (proven best): sl = bb + i*148 (27|28).
    const int nIter = (STG_PER_B - bb + BLK_PER_B - 1) / BLK_PER_B;
    const float* xb = x + (size_t)b * NCLS * NVOX;
    const char*  yb = y + ((size_t)b * NVOX << (y64 ? 3 : 2));

    auto issue = [&](int i) {
        const int off = (bb + i * BLK_PER_B) * TSTG;
        const uint32_t sb = smem_u32 + (uint32_t)((i & (NBUF - 1)) * STAGE_BYTES);
        const int lane64 = tid & 63, grp = tid >> 6;
#pragma unroll
        for (int r = 0; r < 4; r++) {
            const int c = 4 * r + grp;   // 64 threads copy one 1KB class row
            cp16(sb + (uint32_t)(c * (TSTG * 4) + lane64 * 16),
                 xb + (size_t)c * NVOX + off + lane64 * 4);
        }
        if (y64) {
            if (tid < 128)
                cp16(sb + XB_BYTES + tid * 16, yb + (size_t)off * 8 + tid * 16);
        } else {
            if (tid < 64)
                cp16(sb + XB_BYTES + tid * 16, yb + (size_t)off * 4 + tid * 16);
        }
    };

    // Prologue: get 3 stages onto the wire IMMEDIATELY (nIter >= 27 always)...
#pragma unroll
    for (int k = 0; k < NBUF - 1; k++) {
        issue(k);
        asm volatile("cp.async.commit_group;" ::: "memory");
    }

    // ...then zero the bins while those copies are in flight.
#pragma unroll
    for (int c = 0; c < NCLS; c++) s_bin[c][tid] = 0.0f;

    // Counts: classes 0-7 in cLo byte lanes, 8-15 in cHi (max 28 <= 255).
    unsigned long long cLo = 0ull, cHi = 0ull;

    for (int i = 0; i < nIter; i++) {
        asm volatile("cp.async.wait_group 2;" ::: "memory");  // stage i landed
        __syncthreads();   // cross-thread visibility + buffer (i-1) free
        // Refill buffer (i+3)&3 == (i-1)&3, consumed in iter i-1.
        if (i + NBUF - 1 < nIter) issue(i + NBUF - 1);
        asm volatile("cp.async.commit_group;" ::: "memory");

        const char*  stg = dynsmem + (size_t)(i & (NBUF - 1)) * STAGE_BYTES;
        const float* xt  = (const float*)stg;
        const int lab = y64 ? ((const int*)(stg + XB_BYTES))[2 * tid]
                            : ((const int*)(stg + XB_BYTES))[tid];

        float a0 = 0.f, a1 = 0.f, a2 = 0.f, a3 = 0.f;
#pragma unroll
        for (int c = 0; c < NCLS; c += 4) {
            a0 += __expf(xt[(c + 0) * TSTG + tid]);
            a1 += __expf(xt[(c + 1) * TSTG + tid]);
            a2 += __expf(xt[(c + 2) * TSTG + tid]);
            a3 += __expf(xt[(c + 3) * TSTG + tid]);
        }
        const float xl  = xt[lab * TSTG + tid];          // bank tid%32: clean
        const float nll = __logf((a0 + a1) + (a2 + a3)) - xl;

        s_bin[lab][tid] += nll;
        if (lab < 8) cLo += 1ull << (lab * 8);
        else         cHi += 1ull << ((lab - 8) * 8);
    }
    __syncthreads();

    // Phase 1: reduce nll bins. Warp w handles labs {w, w+8}.
    const int w = tid >> 5, l = tid & 31;
#pragma unroll
    for (int lab = w; lab < NCLS; lab += 8) {
        float fs = 0.0f;
#pragma unroll
        for (int k = 0; k < 8; k++) fs += s_bin[lab][l + 32 * k];
#pragma unroll
        for (int o = 16; o > 0; o >>= 1)
            fs += __shfl_xor_sync(0xffffffffu, fs, o);
        if (l == 0) atomicAdd(&g_sum[b * NCLS + lab], fs);
    }
    __syncthreads();

    // Phase 2: reuse s_bin for counts (thread-private slots: plain stores).
#pragma unroll
    for (int c = 0; c < NCLS; c++) {
        const unsigned cc = (unsigned)(((c < 8 ? cLo : cHi) >> ((c & 7) * 8)) & 0xffull);
        s_bin[c][tid] = (float)cc;
    }
    __syncthreads();
#pragma unroll
    for (int lab = w; lab < NCLS; lab += 8) {
        float fs = 0.0f;
#pragma unroll
        for (int k = 0; k < 8; k++) fs += s_bin[lab][l + 32 * k];
#pragma unroll
        for (int o = 16; o > 0; o >>= 1)
            fs += __shfl_xor_sync(0xffffffffu, fs, o);
        if (l == 0) atomicAdd(&g_cnt[b * NCLS + lab], fs);
    }

    // Last-block finalize.
    __threadfence();
    if (tid == 0) {
        unsigned t = atomicAdd(&g_ticket, 1u);
        sh_last = (t == (unsigned)(NBLK - 1)) ? 1 : 0;
    }
    __syncthreads();

    if (sh_last) {
        __threadfence();
        if (tid < NB * NCLS) {
            const float s = atomicAdd(&g_sum[tid], 0.0f);
            const float c = atomicAdd(&g_cnt[tid], 0.0f);
            float m = (c > 0.0f) ? (s / c) : 0.0f;
#pragma unroll
            for (int o = 16; o > 0; o >>= 1)
                m += __shfl_xor_sync(0xffffffffu, m, o);
            if (tid == 0) {
                out[0] = m / (float)(NB * NCLS);
                g_ticket = 0u;
            }
            g_sum[tid] = 0.0f;
            g_cnt[tid] = 0.0f;
        }
    }
}

extern "C" void kernel_launch(void* const* d_in, const int* in_sizes, int n_in,
                              void* d_out, int out_size) {
    const float* x = (const float*)d_in[0];
    const char*  y = (const char*)d_in[1];
    cudaFuncSetAttribute(ce_pipe_kernel,
                         cudaFuncAttributeMaxDynamicSharedMemorySize, DYN_BYTES);
    ce_pipe_kernel<<<NBLK, THREADS, DYN_BYTES>>>(x, y, (float*)d_out);
}